// round 15
// baseline (speedup 1.0000x reference)
#include <cuda_runtime.h>
#include <cstdint>
#include <math.h>

#define FDIM 768
#define HDIM 512
#define BSZ  512
#define NT   256
#define NWORK 64               // worker CTAs (8 rows each)
#define PF   8                 // float4 weight quads prefetched across barriers

// ---------------- device scratch (no allocations allowed) ----------------
__device__ float g_c[FDIM];    // b_ih + b_hh + y_end @ W_hh
__device__ int   g_done = 0;   // ODE-cluster completion counter (reset per call)

// Dormand-Prince 5(4) tableau. Row s = coefficients for stage-s input
// (row 6 = b coefficients -> y_new).
__constant__ float A_TAB[7][6] = {
    {0.f, 0.f, 0.f, 0.f, 0.f, 0.f},
    {1.f/5.f, 0.f, 0.f, 0.f, 0.f, 0.f},
    {3.f/40.f, 9.f/40.f, 0.f, 0.f, 0.f, 0.f},
    {44.f/45.f, -56.f/15.f, 32.f/9.f, 0.f, 0.f, 0.f},
    {19372.f/6561.f, -25360.f/2187.f, 64448.f/6561.f, -212.f/729.f, 0.f, 0.f},
    {9017.f/3168.f, -355.f/33.f, 46732.f/5247.f, 49.f/176.f, -5103.f/18656.f, 0.f},
    {35.f/384.f, 0.f, 500.f/1113.f, 125.f/192.f, -2187.f/6784.f, 11.f/84.f},
};
__constant__ float E_TAB[7] = {
    71.f/57600.f, 0.f, -71.f/16695.f, 71.f/1920.f,
    -17253.f/339200.f, 22.f/525.f, -1.f/40.f
};

__device__ __forceinline__ void cluster_arrive() {
    asm volatile("barrier.cluster.arrive.aligned;" ::: "memory");
}
__device__ __forceinline__ void cluster_wait() {
    asm volatile("barrier.cluster.wait.aligned;" ::: "memory");
}
__device__ __forceinline__ void cluster_sync() {
    cluster_arrive(); cluster_wait();
}
__device__ __forceinline__ uint32_t mapa_u32(uint32_t laddr, uint32_t rank) {
    uint32_t r;
    asm("mapa.shared::cluster.u32 %0, %1, %2;" : "=r"(r) : "r"(laddr), "r"(rank));
    return r;
}
__device__ __forceinline__ void st_cluster_f32(uint32_t addr, float v) {
    asm volatile("st.shared::cluster.f32 [%0], %1;" :: "r"(addr), "f"(v) : "memory");
}
__device__ __forceinline__ float lrelu(float x) { return x > 0.f ? x : 0.1f * x; }

__device__ __forceinline__ void f4fma(float4& a, float s, const float4 w) {
    a.x += s * w.x; a.y += s * w.y; a.z += s * w.z; a.w += s * w.w;
}

// Shared-memory overlay: ODE path and worker path never co-exist in one CTA.
struct OdeSmem {
    float y[FDIM];
    float ynew[FDIM];
    float tmp[FDIM];
    float k[7][FDIM];
    float h1[HDIM];
    float h2[HDIM];
    float part[1216];      // max over CL variants (32*36=1152 / 16*68=1088)
    float red[NT];
};
struct WorkSmem {
    union {
        float h[8][FDIM];            // A rows during GEMM, then h rows
        float part3[2][8][128];      // L3 k-split partials (h dead by then)
    };
    float z1[8][128];
    union {
        float z2[8][256];
        float part1[2][8][128];      // L1 k-split partials (dead before z2)
    };
    float z3[8][128];
};
union SmemU { OdeSmem ode; WorkSmem wk; };

__global__ void reset_kernel() { g_done = 0; }

// =========================================================================
// Fused kernel, templated on ODE cluster size CL (16 opt-in / 8 portable):
//  - blocks 0..CL-1 (cluster 0): Dopri5 ODE solve; column slices
//    partitioned across CL CTAs, DSMEM broadcast of layer outputs.
//    NEW: each layer's cluster barrier is SPLIT (arrive / wait) and the
//    next layer's first PF float4 weight quads are prefetched into
//    registers between them — the ~500cyc barrier wait now overlaps the
//    weight-load latency ramp instead of serializing with it. One wb[PF]
//    buffer is reused across layers (disjoint lifetimes).
//    Ends publishing g_c + threadfence + atomicAdd(g_done).
//  - blocks CL..: worker CTAs — GEMM under the ODE, spin on g_done,
//    epilogue + regressor (unchanged from R8).
// =========================================================================
template <int CL>
__global__ void __launch_bounds__(NT, 1)
fused_kernel(const float* __restrict__ ts,
             const float* __restrict__ w_in,  const float* __restrict__ b_in,
             const float* __restrict__ w_h,   const float* __restrict__ b_h,
             const float* __restrict__ w_out, const float* __restrict__ b_out,
             const float* __restrict__ w_hh,
             const float* __restrict__ b_ih,  const float* __restrict__ b_hh,
             const float* __restrict__ fv,    const float* __restrict__ fi,
             const float* __restrict__ w_ih,
             const float* __restrict__ w1, const float* __restrict__ b1,
             const float* __restrict__ w2, const float* __restrict__ b2,
             const float* __restrict__ w3, const float* __restrict__ b3,
             const float* __restrict__ w4, const float* __restrict__ b4,
             float* __restrict__ pose, float* __restrict__ out_h)
{
    __shared__ __align__(16) SmemU sm;
    const int tid = threadIdx.x;

    if (blockIdx.x >= CL) {
        // ======================= worker path ==============================
        const int base = (blockIdx.x - CL) * 8;   // first batch row

        for (int i = tid * 4; i < 8 * FDIM; i += NT * 4) {
            const int r = i / FDIM, c = i % FDIM;
            const int row = base + r;
            float4 v = (c < 512)
                ? *(const float4*)&fv[(size_t)row * 512 + c]
                : *(const float4*)&fi[(size_t)row * 256 + (c - 512)];
            *(float4*)&sm.wk.h[r][c] = v;
        }
        __syncthreads();

        float acc[3][8];
        #pragma unroll
        for (int q = 0; q < 3; ++q)
            #pragma unroll
            for (int r = 0; r < 8; ++r) acc[q][r] = 0.f;

        #pragma unroll 4
        for (int k = 0; k < FDIM; ++k) {
            const float* wr = w_ih + (size_t)k * FDIM + tid;
            float w0 = wr[0], w1_ = wr[256], w2_ = wr[512];
            #pragma unroll
            for (int r = 0; r < 8; ++r) {
                float a = sm.wk.h[r][k];
                acc[0][r] += a * w0;
                acc[1][r] += a * w1_;
                acc[2][r] += a * w2_;
            }
        }

        if (tid == 0) {
            volatile int* p = &g_done;
            while (*p < CL) __nanosleep(64);
        }
        __syncthreads();
        __threadfence();

        #pragma unroll
        for (int q = 0; q < 3; ++q) {
            const int c = tid + q * 256;
            const float cc = g_c[c];
            #pragma unroll
            for (int r = 0; r < 8; ++r) {
                float v = tanhf(acc[q][r] + cc);
                sm.wk.h[r][c] = v;
                if (out_h) out_h[(size_t)(base + r) * FDIM + c] = v;
            }
        }
        __syncthreads();

        // L1: 768 -> 128, k-split 2x384
        {
            const int j = tid & 127, half = tid >> 7;
            const int k0 = half * 384;
            float a[8] = {};
            #pragma unroll 8
            for (int k = 0; k < 384; ++k) {
                float w = w1[(size_t)(k0 + k) * 128 + j];
                #pragma unroll
                for (int r = 0; r < 8; ++r) a[r] += sm.wk.h[r][k0 + k] * w;
            }
            #pragma unroll
            for (int r = 0; r < 8; ++r) sm.wk.part1[half][r][j] = a[r];
        }
        __syncthreads();
        for (int idx = tid; idx < 8 * 128; idx += NT) {
            const int r = idx >> 7, j = idx & 127;
            sm.wk.z1[r][j] = lrelu(sm.wk.part1[0][r][j] + sm.wk.part1[1][r][j] + b1[j]);
        }
        __syncthreads();

        // L2: 128 -> 256
        {
            float a[8] = {};
            #pragma unroll 8
            for (int k = 0; k < 128; ++k) {
                float w = w2[(size_t)k * 256 + tid];
                #pragma unroll
                for (int r = 0; r < 8; ++r) a[r] += sm.wk.z1[r][k] * w;
            }
            float bb = b2[tid];
            #pragma unroll
            for (int r = 0; r < 8; ++r) sm.wk.z2[r][tid] = lrelu(a[r] + bb);
        }
        __syncthreads();

        // L3: 256 -> 128, k-split 2x128
        {
            const int j = tid & 127, half = tid >> 7;
            const int k0 = half * 128;
            float a[8] = {};
            #pragma unroll 8
            for (int k = 0; k < 128; ++k) {
                float w = w3[(size_t)(k0 + k) * 128 + j];
                #pragma unroll
                for (int r = 0; r < 8; ++r) a[r] += sm.wk.z2[r][k0 + k] * w;
            }
            #pragma unroll
            for (int r = 0; r < 8; ++r) sm.wk.part3[half][r][j] = a[r];
        }
        __syncthreads();
        for (int idx = tid; idx < 8 * 128; idx += NT) {
            const int r = idx >> 7, j = idx & 127;
            sm.wk.z3[r][j] = lrelu(sm.wk.part3[0][r][j] + sm.wk.part3[1][r][j] + b3[j]);
        }
        __syncthreads();

        // L4: 128 -> 6
        if (tid < 48) {
            const int r = tid / 6, j = tid % 6;
            float a = 0.f;
            #pragma unroll 8
            for (int k = 0; k < 128; ++k) a += sm.wk.z3[r][k] * w4[(size_t)k * 6 + j];
            pose[(size_t)(base + r) * 6 + j] = a + b4[j];
        }
        return;
    }

    // ========================= ODE path ===================================
    constexpr int COLS1 = HDIM / CL;     // L1/L2 cols per CTA (64 / 32)
    constexpr int Q1    = COLS1 / 4;
    constexpr int SP1   = NT / Q1;
    constexpr int KL1   = FDIM / SP1;    // (48 / 24)
    constexpr int KL2   = HDIM / SP1;    // (32 / 16)
    constexpr int ST1   = COLS1 + 4;
    constexpr int COLS3 = FDIM / CL;     // L3/tail cols per CTA (96 / 48)
    constexpr int Q3    = COLS3 / 4;
    constexpr int SP3   = 192 / Q3;
    constexpr int KL3   = HDIM / SP3;    // (64 / 32)
    constexpr int KLT   = FDIM / SP3;
    constexpr int ST3   = COLS3 + 4;
    static_assert(PF <= KL2 && PF <= KL1 && PF <= KL3, "PF fits all layers");

    uint32_t rank;
    asm("mov.u32 %0, %%cluster_ctarank;" : "=r"(rank));

    // per-thread loop-invariant addressing
    const int g1i  = tid % Q1, sp1i = tid / Q1;
    const int col1 = (int)rank * COLS1 + g1i * 4;
    const int k0_1 = sp1i * KL1;
    const int k0_2 = sp1i * KL2;
    const float* wp1 = w_in + (size_t)k0_1 * HDIM + col1;
    const float* wp2 = w_h  + (size_t)k0_2 * HDIM + col1;
    const int g3i  = tid % Q3, sp3i = tid / Q3;
    const int col3 = (int)rank * COLS3 + g3i * 4;
    const int k0_3 = sp3i * KL3;
    const float* wp3 = w_out + (size_t)k0_3 * FDIM + col3;   // valid tid<192

    const float t0 = ts[0], t1 = ts[1];
    for (int i = tid; i < FDIM; i += NT) sm.ode.y[i] = 0.f;
    __syncthreads();

    float t  = t0;
    float dt = (t1 - t0) * 0.1f;

    float4 wb[PF];   // cross-barrier weight prefetch buffer (reused per layer)
    #pragma unroll
    for (int p = 0; p < PF; ++p) wb[p] = *(const float4*)(wp1 + (size_t)p * HDIM);

    for (int step = 0; step < 24; ++step) {
        if (t >= t1 - 1e-10f) break;   // frozen state beyond here in reference
        float dt_c = fminf(dt, fmaxf(t1 - t, 1e-10f));

        for (int s = 0; s < 7; ++s) {
            // ---- stage input: tmp = y + dt_c * sum_j a[s][j]*k[j] ----
            for (int i = tid; i < FDIM; i += NT) {
                float acc = 0.f;
                #pragma unroll
                for (int j = 0; j < 6; ++j)
                    if (j < s) acc += A_TAB[s][j] * sm.ode.k[j][i];
                float v = sm.ode.y[i] + dt_c * acc;
                sm.ode.tmp[i] = v;
                if (s == 6) sm.ode.ynew[i] = v;   // stage 7 input is y_new
            }
            __syncthreads();

            // ---- layer 1: tmp[768] @ w_in[768,512] + b_in, tanh ----
            {
                float4 a0 = {0,0,0,0}, a1 = {0,0,0,0};
                #pragma unroll
                for (int k = 0; k < PF; k += 2) {
                    f4fma(a0, sm.ode.tmp[k0_1 + k],     wb[k]);
                    f4fma(a1, sm.ode.tmp[k0_1 + k + 1], wb[k + 1]);
                }
                #pragma unroll
                for (int k = PF; k < KL1; k += 2) {
                    f4fma(a0, sm.ode.tmp[k0_1 + k],     *(const float4*)(wp1 + (size_t)k * HDIM));
                    f4fma(a1, sm.ode.tmp[k0_1 + k + 1], *(const float4*)(wp1 + (size_t)(k + 1) * HDIM));
                }
                a0.x += a1.x; a0.y += a1.y; a0.z += a1.z; a0.w += a1.w;
                *(float4*)&sm.ode.part[sp1i * ST1 + g1i * 4] = a0;
                __syncthreads();
                if (tid < COLS1) {
                    float v = b_in[(int)rank * COLS1 + tid];
                    #pragma unroll
                    for (int p = 0; p < SP1; ++p) v += sm.ode.part[p * ST1 + tid];
                    v = tanhf(v);
                    uint32_t la = (uint32_t)__cvta_generic_to_shared(&sm.ode.h1[(int)rank * COLS1 + tid]);
                    #pragma unroll
                    for (int r = 0; r < CL; ++r)
                        st_cluster_f32(mapa_u32(la, (uint32_t)r), v);
                }
                cluster_arrive();
                #pragma unroll
                for (int p = 0; p < PF; ++p) wb[p] = *(const float4*)(wp2 + (size_t)p * HDIM);
                cluster_wait();
            }

            // ---- layer 2: h1[512] @ w_h[512,512] + b_h, tanh ----
            {
                float4 a0 = {0,0,0,0}, a1 = {0,0,0,0};
                #pragma unroll
                for (int k = 0; k < PF; k += 2) {
                    f4fma(a0, sm.ode.h1[k0_2 + k],     wb[k]);
                    f4fma(a1, sm.ode.h1[k0_2 + k + 1], wb[k + 1]);
                }
                #pragma unroll
                for (int k = PF; k < KL2; k += 2) {
                    f4fma(a0, sm.ode.h1[k0_2 + k],     *(const float4*)(wp2 + (size_t)k * HDIM));
                    f4fma(a1, sm.ode.h1[k0_2 + k + 1], *(const float4*)(wp2 + (size_t)(k + 1) * HDIM));
                }
                a0.x += a1.x; a0.y += a1.y; a0.z += a1.z; a0.w += a1.w;
                *(float4*)&sm.ode.part[sp1i * ST1 + g1i * 4] = a0;
                __syncthreads();
                if (tid < COLS1) {
                    float v = b_h[(int)rank * COLS1 + tid];
                    #pragma unroll
                    for (int p = 0; p < SP1; ++p) v += sm.ode.part[p * ST1 + tid];
                    v = tanhf(v);
                    uint32_t la = (uint32_t)__cvta_generic_to_shared(&sm.ode.h2[(int)rank * COLS1 + tid]);
                    #pragma unroll
                    for (int r = 0; r < CL; ++r)
                        st_cluster_f32(mapa_u32(la, (uint32_t)r), v);
                }
                cluster_arrive();
                if (tid < 192) {
                    #pragma unroll
                    for (int p = 0; p < PF; ++p) wb[p] = *(const float4*)(wp3 + (size_t)p * FDIM);
                }
                cluster_wait();
            }

            // ---- layer 3: h2[512] @ w_out[512,768] + b_out -> k[s] ----
            {
                if (tid < 192) {
                    float4 a0 = {0,0,0,0}, a1 = {0,0,0,0};
                    #pragma unroll
                    for (int k = 0; k < PF; k += 2) {
                        f4fma(a0, sm.ode.h2[k0_3 + k],     wb[k]);
                        f4fma(a1, sm.ode.h2[k0_3 + k + 1], wb[k + 1]);
                    }
                    #pragma unroll
                    for (int k = PF; k < KL3; k += 2) {
                        f4fma(a0, sm.ode.h2[k0_3 + k],     *(const float4*)(wp3 + (size_t)k * FDIM));
                        f4fma(a1, sm.ode.h2[k0_3 + k + 1], *(const float4*)(wp3 + (size_t)(k + 1) * FDIM));
                    }
                    a0.x += a1.x; a0.y += a1.y; a0.z += a1.z; a0.w += a1.w;
                    *(float4*)&sm.ode.part[sp3i * ST3 + g3i * 4] = a0;
                }
                __syncthreads();
                if (tid < COLS3) {
                    float v = b_out[(int)rank * COLS3 + tid];
                    #pragma unroll
                    for (int p = 0; p < SP3; ++p) v += sm.ode.part[p * ST3 + tid];
                    uint32_t la = (uint32_t)__cvta_generic_to_shared(&sm.ode.k[s][(int)rank * COLS3 + tid]);
                    #pragma unroll
                    for (int r = 0; r < CL; ++r)
                        st_cluster_f32(mapa_u32(la, (uint32_t)r), v);
                }
                cluster_arrive();
                #pragma unroll
                for (int p = 0; p < PF; ++p) wb[p] = *(const float4*)(wp1 + (size_t)p * HDIM);
                cluster_wait();
            }
        } // stages

        // ---- error norm + step control (redundant per CTA, identical) ----
        float lsum = 0.f;
        for (int i = tid; i < FDIM; i += NT) {
            float e = E_TAB[0] * sm.ode.k[0][i] + E_TAB[2] * sm.ode.k[2][i]
                    + E_TAB[3] * sm.ode.k[3][i] + E_TAB[4] * sm.ode.k[4][i]
                    + E_TAB[5] * sm.ode.k[5][i] + E_TAB[6] * sm.ode.k[6][i];
            float err = dt_c * e;
            float tol = 1e-6f + 1e-3f * fmaxf(fabsf(sm.ode.y[i]), fabsf(sm.ode.ynew[i]));
            float r = err / tol;
            lsum += r * r;
        }
        sm.ode.red[tid] = lsum;
        __syncthreads();
        for (int off = NT / 2; off > 0; off >>= 1) {
            if (tid < off) sm.ode.red[tid] += sm.ode.red[tid + off];
            __syncthreads();
        }
        float norm = sqrtf(sm.ode.red[0] / (float)FDIM);
        __syncthreads();

        bool accept = (norm <= 1.0f);
        if (accept) {
            for (int i = tid; i < FDIM; i += NT) sm.ode.y[i] = sm.ode.ynew[i];
            t = t + dt_c;
        }
        float factor = 0.9f * powf(fmaxf(norm, 1e-10f), -0.2f);
        factor = fminf(fmaxf(factor, 0.2f), 10.f);
        dt = dt_c * factor;
        __syncthreads();
    }

    // ---- tail: g_c = b_ih + b_hh + y_end @ w_hh (768x768 matvec) ----
    {
        if (tid < 192) {
            const int k0 = sp3i * KLT;
            const float* wp = w_hh + (size_t)k0 * FDIM + col3;
            float4 a0 = {0,0,0,0}, a1 = {0,0,0,0};
            #pragma unroll
            for (int k = 0; k < KLT; k += 2) {
                f4fma(a0, sm.ode.y[k0 + k],     *(const float4*)(wp + (size_t)k * FDIM));
                f4fma(a1, sm.ode.y[k0 + k + 1], *(const float4*)(wp + (size_t)(k + 1) * FDIM));
            }
            a0.x += a1.x; a0.y += a1.y; a0.z += a1.z; a0.w += a1.w;
            *(float4*)&sm.ode.part[sp3i * ST3 + g3i * 4] = a0;
        }
        __syncthreads();
        if (tid < COLS3) {
            const int col = (int)rank * COLS3 + tid;
            float v = b_ih[col] + b_hh[col];
            #pragma unroll
            for (int p = 0; p < SP3; ++p) v += sm.ode.part[p * ST3 + tid];
            g_c[col] = v;
        }
        __threadfence();          // make this CTA's g_c slice globally visible
        __syncthreads();
        if (tid == 0) atomicAdd(&g_done, 1);   // arrive (CL total)
    }
}

// =========================================================================
extern "C" void kernel_launch(void* const* d_in, const int* in_sizes, int n_in,
                              void* d_out, int out_size)
{
    const float* fv       = (const float*)d_in[0];
    const float* fi       = (const float*)d_in[2];
    const float* ts       = (const float*)d_in[4];
    const float* ode_w_in = (const float*)d_in[5];
    const float* ode_b_in = (const float*)d_in[6];
    const float* ode_w_h  = (const float*)d_in[7];
    const float* ode_b_h  = (const float*)d_in[8];
    const float* ode_w_out= (const float*)d_in[9];
    const float* ode_b_out= (const float*)d_in[10];
    const float* rnn_w_ih = (const float*)d_in[11];
    const float* rnn_w_hh = (const float*)d_in[12];
    const float* rnn_b_ih = (const float*)d_in[13];
    const float* rnn_b_hh = (const float*)d_in[14];
    const float* rw1 = (const float*)d_in[15];
    const float* rb1 = (const float*)d_in[16];
    const float* rw2 = (const float*)d_in[17];
    const float* rb2 = (const float*)d_in[18];
    const float* rw3 = (const float*)d_in[19];
    const float* rb3 = (const float*)d_in[20];
    const float* rw4 = (const float*)d_in[21];
    const float* rb4 = (const float*)d_in[22];

    float* pose_out = (float*)d_out;
    float* h_out = (out_size >= BSZ * 6 + BSZ * FDIM)
                       ? ((float*)d_out + BSZ * 6) : nullptr;

    reset_kernel<<<1, 1>>>();

    // Decide cluster width from the attribute-set result ONLY (host-side,
    // capture-safe, deterministic). Exactly one fused_kernel launch per call.
    static cudaError_t aerr = cudaFuncSetAttribute(
        (const void*)fused_kernel<16>,
        cudaFuncAttributeNonPortableClusterSizeAllowed, 1);

    if (aerr == cudaSuccess) {
        cudaLaunchConfig_t cfg = {};
        cfg.gridDim  = dim3(16 + NWORK, 1, 1);   // 80 = 5 clusters of 16
        cfg.blockDim = dim3(NT, 1, 1);
        cfg.dynamicSmemBytes = 0;
        cfg.stream = 0;
        cudaLaunchAttribute at[1];
        at[0].id = cudaLaunchAttributeClusterDimension;
        at[0].val.clusterDim = {16, 1, 1};
        cfg.attrs = at;
        cfg.numAttrs = 1;
        cudaLaunchKernelEx(&cfg, fused_kernel<16>,
            ts, ode_w_in, ode_b_in, ode_w_h, ode_b_h, ode_w_out, ode_b_out,
            rnn_w_hh, rnn_b_ih, rnn_b_hh, fv, fi, rnn_w_ih,
            rw1, rb1, rw2, rb2, rw3, rb3, rw4, rb4, pose_out, h_out);
    } else {
        cudaLaunchConfig_t cfg = {};
        cfg.gridDim  = dim3(8 + NWORK, 1, 1);    // 72 = 9 clusters of 8
        cfg.blockDim = dim3(NT, 1, 1);
        cfg.dynamicSmemBytes = 0;
        cfg.stream = 0;
        cudaLaunchAttribute at[1];
        at[0].id = cudaLaunchAttributeClusterDimension;
        at[0].val.clusterDim = {8, 1, 1};
        cfg.attrs = at;
        cfg.numAttrs = 1;
        cudaLaunchKernelEx(&cfg, fused_kernel<8>,
            ts, ode_w_in, ode_b_in, ode_w_h, ode_b_h, ode_w_out, ode_b_out,
            rnn_w_hh, rnn_b_ih, rnn_b_hh, fv, fi, rnn_w_ih,
            rw1, rb1, rw2, rb2, rw3, rb3, rw4, rb4, pose_out, h_out);
    }
}

// round 16
// speedup vs baseline: 1.0212x; 1.0212x over previous
#include <cuda_runtime.h>
#include <cstdint>
#include <math.h>

#define FDIM 768
#define HDIM 512
#define BSZ  512
#define NT   256
#define NWORK 64               // worker CTAs (8 rows each)
#define PF   12                // float4 weight quads prefetched across barriers

// ---------------- device scratch (no allocations allowed) ----------------
__device__ float g_c[FDIM];    // b_ih + b_hh + y_end @ W_hh
__device__ int   g_done = 0;   // ODE-cluster completion counter (reset per call)

// Dormand-Prince 5(4) tableau. Row s = coefficients for stage-s input
// (row 6 = b coefficients -> y_new).
__constant__ float A_TAB[7][6] = {
    {0.f, 0.f, 0.f, 0.f, 0.f, 0.f},
    {1.f/5.f, 0.f, 0.f, 0.f, 0.f, 0.f},
    {3.f/40.f, 9.f/40.f, 0.f, 0.f, 0.f, 0.f},
    {44.f/45.f, -56.f/15.f, 32.f/9.f, 0.f, 0.f, 0.f},
    {19372.f/6561.f, -25360.f/2187.f, 64448.f/6561.f, -212.f/729.f, 0.f, 0.f},
    {9017.f/3168.f, -355.f/33.f, 46732.f/5247.f, 49.f/176.f, -5103.f/18656.f, 0.f},
    {35.f/384.f, 0.f, 500.f/1113.f, 125.f/192.f, -2187.f/6784.f, 11.f/84.f},
};
__constant__ float E_TAB[7] = {
    71.f/57600.f, 0.f, -71.f/16695.f, 71.f/1920.f,
    -17253.f/339200.f, 22.f/525.f, -1.f/40.f
};

__device__ __forceinline__ void cluster_arrive() {
    asm volatile("barrier.cluster.arrive.aligned;" ::: "memory");
}
__device__ __forceinline__ void cluster_wait() {
    asm volatile("barrier.cluster.wait.aligned;" ::: "memory");
}
__device__ __forceinline__ uint32_t mapa_u32(uint32_t laddr, uint32_t rank) {
    uint32_t r;
    asm("mapa.shared::cluster.u32 %0, %1, %2;" : "=r"(r) : "r"(laddr), "r"(rank));
    return r;
}
__device__ __forceinline__ void st_cluster_f32(uint32_t addr, float v) {
    asm volatile("st.shared::cluster.f32 [%0], %1;" :: "r"(addr), "f"(v) : "memory");
}
__device__ __forceinline__ float lrelu(float x) { return x > 0.f ? x : 0.1f * x; }

__device__ __forceinline__ void f4fma(float4& a, float s, const float4 w) {
    a.x += s * w.x; a.y += s * w.y; a.z += s * w.z; a.w += s * w.w;
}

// Shared-memory overlay: ODE path and worker path never co-exist in one CTA.
struct OdeSmem {
    float y[FDIM];
    float ynew[FDIM];
    float tmp[FDIM];
    float k[7][FDIM];
    float h1[HDIM];
    float h2[HDIM];
    float part[1216];      // max over CL variants (32*36=1152 / 16*68=1088)
    float red[NT];
};
struct WorkSmem {
    union {
        float h[8][FDIM];            // A rows during GEMM, then h rows
        float part3[2][8][128];      // L3 k-split partials (h dead by then)
    };
    float z1[8][128];
    union {
        float z2[8][256];
        float part1[2][8][128];      // L1 k-split partials (dead before z2)
    };
    float z3[8][128];
};
union SmemU { OdeSmem ode; WorkSmem wk; };

__global__ void reset_kernel() { g_done = 0; }

// =========================================================================
// Fused kernel, templated on ODE cluster size CL (16 opt-in / 8 portable):
//  - blocks 0..CL-1 (cluster 0): Dopri5 ODE solve with FSAL: after step 0,
//    stage s=0 (k1 = f(y)) is never recomputed — on accept k[6] (= f(y_new),
//    bit-identical to next step's f(y)) is copied into k[0]; on reject k[0]
//    is already f(y). Saves one full f-eval (3 matvecs + 3 barriers)/step.
//    Split cluster barriers with PF-quad register prefetch of the next
//    layer's weights between arrive and wait (R15 pattern, PF 8->12).
//    Ends publishing g_c + threadfence + atomicAdd(g_done).
//  - blocks CL..: worker CTAs — GEMM under the ODE, spin on g_done,
//    epilogue + regressor (unchanged from R8).
// =========================================================================
template <int CL>
__global__ void __launch_bounds__(NT, 1)
fused_kernel(const float* __restrict__ ts,
             const float* __restrict__ w_in,  const float* __restrict__ b_in,
             const float* __restrict__ w_h,   const float* __restrict__ b_h,
             const float* __restrict__ w_out, const float* __restrict__ b_out,
             const float* __restrict__ w_hh,
             const float* __restrict__ b_ih,  const float* __restrict__ b_hh,
             const float* __restrict__ fv,    const float* __restrict__ fi,
             const float* __restrict__ w_ih,
             const float* __restrict__ w1, const float* __restrict__ b1,
             const float* __restrict__ w2, const float* __restrict__ b2,
             const float* __restrict__ w3, const float* __restrict__ b3,
             const float* __restrict__ w4, const float* __restrict__ b4,
             float* __restrict__ pose, float* __restrict__ out_h)
{
    __shared__ __align__(16) SmemU sm;
    const int tid = threadIdx.x;

    if (blockIdx.x >= CL) {
        // ======================= worker path ==============================
        const int base = (blockIdx.x - CL) * 8;   // first batch row

        for (int i = tid * 4; i < 8 * FDIM; i += NT * 4) {
            const int r = i / FDIM, c = i % FDIM;
            const int row = base + r;
            float4 v = (c < 512)
                ? *(const float4*)&fv[(size_t)row * 512 + c]
                : *(const float4*)&fi[(size_t)row * 256 + (c - 512)];
            *(float4*)&sm.wk.h[r][c] = v;
        }
        __syncthreads();

        float acc[3][8];
        #pragma unroll
        for (int q = 0; q < 3; ++q)
            #pragma unroll
            for (int r = 0; r < 8; ++r) acc[q][r] = 0.f;

        #pragma unroll 4
        for (int k = 0; k < FDIM; ++k) {
            const float* wr = w_ih + (size_t)k * FDIM + tid;
            float w0 = wr[0], w1_ = wr[256], w2_ = wr[512];
            #pragma unroll
            for (int r = 0; r < 8; ++r) {
                float a = sm.wk.h[r][k];
                acc[0][r] += a * w0;
                acc[1][r] += a * w1_;
                acc[2][r] += a * w2_;
            }
        }

        if (tid == 0) {
            volatile int* p = &g_done;
            while (*p < CL) __nanosleep(64);
        }
        __syncthreads();
        __threadfence();

        #pragma unroll
        for (int q = 0; q < 3; ++q) {
            const int c = tid + q * 256;
            const float cc = g_c[c];
            #pragma unroll
            for (int r = 0; r < 8; ++r) {
                float v = tanhf(acc[q][r] + cc);
                sm.wk.h[r][c] = v;
                if (out_h) out_h[(size_t)(base + r) * FDIM + c] = v;
            }
        }
        __syncthreads();

        // L1: 768 -> 128, k-split 2x384
        {
            const int j = tid & 127, half = tid >> 7;
            const int k0 = half * 384;
            float a[8] = {};
            #pragma unroll 8
            for (int k = 0; k < 384; ++k) {
                float w = w1[(size_t)(k0 + k) * 128 + j];
                #pragma unroll
                for (int r = 0; r < 8; ++r) a[r] += sm.wk.h[r][k0 + k] * w;
            }
            #pragma unroll
            for (int r = 0; r < 8; ++r) sm.wk.part1[half][r][j] = a[r];
        }
        __syncthreads();
        for (int idx = tid; idx < 8 * 128; idx += NT) {
            const int r = idx >> 7, j = idx & 127;
            sm.wk.z1[r][j] = lrelu(sm.wk.part1[0][r][j] + sm.wk.part1[1][r][j] + b1[j]);
        }
        __syncthreads();

        // L2: 128 -> 256
        {
            float a[8] = {};
            #pragma unroll 8
            for (int k = 0; k < 128; ++k) {
                float w = w2[(size_t)k * 256 + tid];
                #pragma unroll
                for (int r = 0; r < 8; ++r) a[r] += sm.wk.z1[r][k] * w;
            }
            float bb = b2[tid];
            #pragma unroll
            for (int r = 0; r < 8; ++r) sm.wk.z2[r][tid] = lrelu(a[r] + bb);
        }
        __syncthreads();

        // L3: 256 -> 128, k-split 2x128
        {
            const int j = tid & 127, half = tid >> 7;
            const int k0 = half * 128;
            float a[8] = {};
            #pragma unroll 8
            for (int k = 0; k < 128; ++k) {
                float w = w3[(size_t)(k0 + k) * 128 + j];
                #pragma unroll
                for (int r = 0; r < 8; ++r) a[r] += sm.wk.z2[r][k0 + k] * w;
            }
            #pragma unroll
            for (int r = 0; r < 8; ++r) sm.wk.part3[half][r][j] = a[r];
        }
        __syncthreads();
        for (int idx = tid; idx < 8 * 128; idx += NT) {
            const int r = idx >> 7, j = idx & 127;
            sm.wk.z3[r][j] = lrelu(sm.wk.part3[0][r][j] + sm.wk.part3[1][r][j] + b3[j]);
        }
        __syncthreads();

        // L4: 128 -> 6
        if (tid < 48) {
            const int r = tid / 6, j = tid % 6;
            float a = 0.f;
            #pragma unroll 8
            for (int k = 0; k < 128; ++k) a += sm.wk.z3[r][k] * w4[(size_t)k * 6 + j];
            pose[(size_t)(base + r) * 6 + j] = a + b4[j];
        }
        return;
    }

    // ========================= ODE path ===================================
    constexpr int COLS1 = HDIM / CL;     // L1/L2 cols per CTA (64 / 32)
    constexpr int Q1    = COLS1 / 4;
    constexpr int SP1   = NT / Q1;
    constexpr int KL1   = FDIM / SP1;    // (48 / 24)
    constexpr int KL2   = HDIM / SP1;    // (32 / 16)
    constexpr int ST1   = COLS1 + 4;
    constexpr int COLS3 = FDIM / CL;     // L3/tail cols per CTA (96 / 48)
    constexpr int Q3    = COLS3 / 4;
    constexpr int SP3   = 192 / Q3;
    constexpr int KL3   = HDIM / SP3;    // (64 / 32)
    constexpr int KLT   = FDIM / SP3;
    constexpr int ST3   = COLS3 + 4;
    static_assert(PF <= KL2 && PF <= KL1 && PF <= KL3, "PF fits all layers");

    uint32_t rank;
    asm("mov.u32 %0, %%cluster_ctarank;" : "=r"(rank));

    // per-thread loop-invariant addressing
    const int g1i  = tid % Q1, sp1i = tid / Q1;
    const int col1 = (int)rank * COLS1 + g1i * 4;
    const int k0_1 = sp1i * KL1;
    const int k0_2 = sp1i * KL2;
    const float* wp1 = w_in + (size_t)k0_1 * HDIM + col1;
    const float* wp2 = w_h  + (size_t)k0_2 * HDIM + col1;
    const int g3i  = tid % Q3, sp3i = tid / Q3;
    const int col3 = (int)rank * COLS3 + g3i * 4;
    const int k0_3 = sp3i * KL3;
    const float* wp3 = w_out + (size_t)k0_3 * FDIM + col3;   // valid tid<192

    const float t0 = ts[0], t1 = ts[1];
    for (int i = tid; i < FDIM; i += NT) sm.ode.y[i] = 0.f;
    __syncthreads();

    float t  = t0;
    float dt = (t1 - t0) * 0.1f;

    float4 wb[PF];   // cross-barrier weight prefetch buffer (reused per layer)
    #pragma unroll
    for (int p = 0; p < PF; ++p) wb[p] = *(const float4*)(wp1 + (size_t)p * HDIM);

    for (int step = 0; step < 24; ++step) {
        if (t >= t1 - 1e-10f) break;   // frozen state beyond here in reference
        float dt_c = fminf(dt, fmaxf(t1 - t, 1e-10f));

        // FSAL: after step 0, k[0] already holds f(y) (copied from k[6] on
        // accept — bit-identical since stage-7 input == y_new == y — or left
        // untouched on reject). Skip stage 0 entirely.
        const int s_first = (step == 0) ? 0 : 1;

        for (int s = s_first; s < 7; ++s) {
            // ---- stage input: tmp = y + dt_c * sum_j a[s][j]*k[j] ----
            for (int i = tid; i < FDIM; i += NT) {
                float acc = 0.f;
                #pragma unroll
                for (int j = 0; j < 6; ++j)
                    if (j < s) acc += A_TAB[s][j] * sm.ode.k[j][i];
                float v = sm.ode.y[i] + dt_c * acc;
                sm.ode.tmp[i] = v;
                if (s == 6) sm.ode.ynew[i] = v;   // stage 7 input is y_new
            }
            __syncthreads();

            // ---- layer 1: tmp[768] @ w_in[768,512] + b_in, tanh ----
            {
                float4 a0 = {0,0,0,0}, a1 = {0,0,0,0};
                #pragma unroll
                for (int k = 0; k < PF; k += 2) {
                    f4fma(a0, sm.ode.tmp[k0_1 + k],     wb[k]);
                    f4fma(a1, sm.ode.tmp[k0_1 + k + 1], wb[k + 1]);
                }
                #pragma unroll
                for (int k = PF; k < KL1; k += 2) {
                    f4fma(a0, sm.ode.tmp[k0_1 + k],     *(const float4*)(wp1 + (size_t)k * HDIM));
                    f4fma(a1, sm.ode.tmp[k0_1 + k + 1], *(const float4*)(wp1 + (size_t)(k + 1) * HDIM));
                }
                a0.x += a1.x; a0.y += a1.y; a0.z += a1.z; a0.w += a1.w;
                *(float4*)&sm.ode.part[sp1i * ST1 + g1i * 4] = a0;
                __syncthreads();
                if (tid < COLS1) {
                    float v = b_in[(int)rank * COLS1 + tid];
                    #pragma unroll
                    for (int p = 0; p < SP1; ++p) v += sm.ode.part[p * ST1 + tid];
                    v = tanhf(v);
                    uint32_t la = (uint32_t)__cvta_generic_to_shared(&sm.ode.h1[(int)rank * COLS1 + tid]);
                    #pragma unroll
                    for (int r = 0; r < CL; ++r)
                        st_cluster_f32(mapa_u32(la, (uint32_t)r), v);
                }
                cluster_arrive();
                #pragma unroll
                for (int p = 0; p < PF; ++p) wb[p] = *(const float4*)(wp2 + (size_t)p * HDIM);
                cluster_wait();
            }

            // ---- layer 2: h1[512] @ w_h[512,512] + b_h, tanh ----
            {
                float4 a0 = {0,0,0,0}, a1 = {0,0,0,0};
                #pragma unroll
                for (int k = 0; k < PF; k += 2) {
                    f4fma(a0, sm.ode.h1[k0_2 + k],     wb[k]);
                    f4fma(a1, sm.ode.h1[k0_2 + k + 1], wb[k + 1]);
                }
                #pragma unroll
                for (int k = PF; k < KL2; k += 2) {
                    f4fma(a0, sm.ode.h1[k0_2 + k],     *(const float4*)(wp2 + (size_t)k * HDIM));
                    f4fma(a1, sm.ode.h1[k0_2 + k + 1], *(const float4*)(wp2 + (size_t)(k + 1) * HDIM));
                }
                a0.x += a1.x; a0.y += a1.y; a0.z += a1.z; a0.w += a1.w;
                *(float4*)&sm.ode.part[sp1i * ST1 + g1i * 4] = a0;
                __syncthreads();
                if (tid < COLS1) {
                    float v = b_h[(int)rank * COLS1 + tid];
                    #pragma unroll
                    for (int p = 0; p < SP1; ++p) v += sm.ode.part[p * ST1 + tid];
                    v = tanhf(v);
                    uint32_t la = (uint32_t)__cvta_generic_to_shared(&sm.ode.h2[(int)rank * COLS1 + tid]);
                    #pragma unroll
                    for (int r = 0; r < CL; ++r)
                        st_cluster_f32(mapa_u32(la, (uint32_t)r), v);
                }
                cluster_arrive();
                if (tid < 192) {
                    #pragma unroll
                    for (int p = 0; p < PF; ++p) wb[p] = *(const float4*)(wp3 + (size_t)p * FDIM);
                }
                cluster_wait();
            }

            // ---- layer 3: h2[512] @ w_out[512,768] + b_out -> k[s] ----
            {
                if (tid < 192) {
                    float4 a0 = {0,0,0,0}, a1 = {0,0,0,0};
                    #pragma unroll
                    for (int k = 0; k < PF; k += 2) {
                        f4fma(a0, sm.ode.h2[k0_3 + k],     wb[k]);
                        f4fma(a1, sm.ode.h2[k0_3 + k + 1], wb[k + 1]);
                    }
                    #pragma unroll
                    for (int k = PF; k < KL3; k += 2) {
                        f4fma(a0, sm.ode.h2[k0_3 + k],     *(const float4*)(wp3 + (size_t)k * FDIM));
                        f4fma(a1, sm.ode.h2[k0_3 + k + 1], *(const float4*)(wp3 + (size_t)(k + 1) * FDIM));
                    }
                    a0.x += a1.x; a0.y += a1.y; a0.z += a1.z; a0.w += a1.w;
                    *(float4*)&sm.ode.part[sp3i * ST3 + g3i * 4] = a0;
                }
                __syncthreads();
                if (tid < COLS3) {
                    float v = b_out[(int)rank * COLS3 + tid];
                    #pragma unroll
                    for (int p = 0; p < SP3; ++p) v += sm.ode.part[p * ST3 + tid];
                    uint32_t la = (uint32_t)__cvta_generic_to_shared(&sm.ode.k[s][(int)rank * COLS3 + tid]);
                    #pragma unroll
                    for (int r = 0; r < CL; ++r)
                        st_cluster_f32(mapa_u32(la, (uint32_t)r), v);
                }
                cluster_arrive();
                #pragma unroll
                for (int p = 0; p < PF; ++p) wb[p] = *(const float4*)(wp1 + (size_t)p * HDIM);
                cluster_wait();
            }
        } // stages

        // ---- error norm + step control (redundant per CTA, identical) ----
        float lsum = 0.f;
        for (int i = tid; i < FDIM; i += NT) {
            float e = E_TAB[0] * sm.ode.k[0][i] + E_TAB[2] * sm.ode.k[2][i]
                    + E_TAB[3] * sm.ode.k[3][i] + E_TAB[4] * sm.ode.k[4][i]
                    + E_TAB[5] * sm.ode.k[5][i] + E_TAB[6] * sm.ode.k[6][i];
            float err = dt_c * e;
            float tol = 1e-6f + 1e-3f * fmaxf(fabsf(sm.ode.y[i]), fabsf(sm.ode.ynew[i]));
            float r = err / tol;
            lsum += r * r;
        }
        sm.ode.red[tid] = lsum;
        __syncthreads();
        for (int off = NT / 2; off > 0; off >>= 1) {
            if (tid < off) sm.ode.red[tid] += sm.ode.red[tid + off];
            __syncthreads();
        }
        float norm = sqrtf(sm.ode.red[0] / (float)FDIM);
        __syncthreads();

        bool accept = (norm <= 1.0f);
        if (accept) {
            // FSAL: k[6] = f(y_new) becomes next step's k[0] = f(y).
            for (int i = tid; i < FDIM; i += NT) {
                sm.ode.y[i] = sm.ode.ynew[i];
                sm.ode.k[0][i] = sm.ode.k[6][i];
            }
            t = t + dt_c;
        }
        float factor = 0.9f * powf(fmaxf(norm, 1e-10f), -0.2f);
        factor = fminf(fmaxf(factor, 0.2f), 10.f);
        dt = dt_c * factor;
        __syncthreads();
    }

    // ---- tail: g_c = b_ih + b_hh + y_end @ w_hh (768x768 matvec) ----
    {
        if (tid < 192) {
            const int k0 = sp3i * KLT;
            const float* wp = w_hh + (size_t)k0 * FDIM + col3;
            float4 a0 = {0,0,0,0}, a1 = {0,0,0,0};
            #pragma unroll
            for (int k = 0; k < KLT; k += 2) {
                f4fma(a0, sm.ode.y[k0 + k],     *(const float4*)(wp + (size_t)k * FDIM));
                f4fma(a1, sm.ode.y[k0 + k + 1], *(const float4*)(wp + (size_t)(k + 1) * FDIM));
            }
            a0.x += a1.x; a0.y += a1.y; a0.z += a1.z; a0.w += a1.w;
            *(float4*)&sm.ode.part[sp3i * ST3 + g3i * 4] = a0;
        }
        __syncthreads();
        if (tid < COLS3) {
            const int col = (int)rank * COLS3 + tid;
            float v = b_ih[col] + b_hh[col];
            #pragma unroll
            for (int p = 0; p < SP3; ++p) v += sm.ode.part[p * ST3 + tid];
            g_c[col] = v;
        }
        __threadfence();          // make this CTA's g_c slice globally visible
        __syncthreads();
        if (tid == 0) atomicAdd(&g_done, 1);   // arrive (CL total)
    }
}

// =========================================================================
extern "C" void kernel_launch(void* const* d_in, const int* in_sizes, int n_in,
                              void* d_out, int out_size)
{
    const float* fv       = (const float*)d_in[0];
    const float* fi       = (const float*)d_in[2];
    const float* ts       = (const float*)d_in[4];
    const float* ode_w_in = (const float*)d_in[5];
    const float* ode_b_in = (const float*)d_in[6];
    const float* ode_w_h  = (const float*)d_in[7];
    const float* ode_b_h  = (const float*)d_in[8];
    const float* ode_w_out= (const float*)d_in[9];
    const float* ode_b_out= (const float*)d_in[10];
    const float* rnn_w_ih = (const float*)d_in[11];
    const float* rnn_w_hh = (const float*)d_in[12];
    const float* rnn_b_ih = (const float*)d_in[13];
    const float* rnn_b_hh = (const float*)d_in[14];
    const float* rw1 = (const float*)d_in[15];
    const float* rb1 = (const float*)d_in[16];
    const float* rw2 = (const float*)d_in[17];
    const float* rb2 = (const float*)d_in[18];
    const float* rw3 = (const float*)d_in[19];
    const float* rb3 = (const float*)d_in[20];
    const float* rw4 = (const float*)d_in[21];
    const float* rb4 = (const float*)d_in[22];

    float* pose_out = (float*)d_out;
    float* h_out = (out_size >= BSZ * 6 + BSZ * FDIM)
                       ? ((float*)d_out + BSZ * 6) : nullptr;

    reset_kernel<<<1, 1>>>();

    // Decide cluster width from the attribute-set result ONLY (host-side,
    // capture-safe, deterministic). Exactly one fused_kernel launch per call.
    static cudaError_t aerr = cudaFuncSetAttribute(
        (const void*)fused_kernel<16>,
        cudaFuncAttributeNonPortableClusterSizeAllowed, 1);

    if (aerr == cudaSuccess) {
        cudaLaunchConfig_t cfg = {};
        cfg.gridDim  = dim3(16 + NWORK, 1, 1);   // 80 = 5 clusters of 16
        cfg.blockDim = dim3(NT, 1, 1);
        cfg.dynamicSmemBytes = 0;
        cfg.stream = 0;
        cudaLaunchAttribute at[1];
        at[0].id = cudaLaunchAttributeClusterDimension;
        at[0].val.clusterDim = {16, 1, 1};
        cfg.attrs = at;
        cfg.numAttrs = 1;
        cudaLaunchKernelEx(&cfg, fused_kernel<16>,
            ts, ode_w_in, ode_b_in, ode_w_h, ode_b_h, ode_w_out, ode_b_out,
            rnn_w_hh, rnn_b_ih, rnn_b_hh, fv, fi, rnn_w_ih,
            rw1, rb1, rw2, rb2, rw3, rb3, rw4, rb4, pose_out, h_out);
    } else {
        cudaLaunchConfig_t cfg = {};
        cfg.gridDim  = dim3(8 + NWORK, 1, 1);    // 72 = 9 clusters of 8
        cfg.blockDim = dim3(NT, 1, 1);
        cfg.dynamicSmemBytes = 0;
        cfg.stream = 0;
        cudaLaunchAttribute at[1];
        at[0].id = cudaLaunchAttributeClusterDimension;
        at[0].val.clusterDim = {8, 1, 1};
        cfg.attrs = at;
        cfg.numAttrs = 1;
        cudaLaunchKernelEx(&cfg, fused_kernel<8>,
            ts, ode_w_in, ode_b_in, ode_w_h, ode_b_h, ode_w_out, ode_b_out,
            rnn_w_hh, rnn_b_ih, rnn_b_hh, fv, fi, rnn_w_ih,
            rw1, rb1, rw2, rb2, rw3, rb3, rw4, rb4, pose_out, h_out);
    }
}